// round 7
// baseline (speedup 1.0000x reference)
#include <cuda_runtime.h>
#include <math.h>

// 2-layer GATv2 (H=2 heads, C=32 ch) + edge MLP.
// N=50000 nodes, E=800000 edges (+N self loops). Output: E float logits.

#define HC 64
#define CC 32
#define MAXN 65536
#define MAXE 1048576
#define MAXEP (MAXE + MAXN)

// ---- device scratch (static) ----
__device__ float  g_z[MAXN * HC];
__device__ float  g_hA[MAXN * HC];
__device__ float  g_hB[MAXN * HC];
__device__ int    g_deg[MAXN];
__device__ int    g_off[MAXN];
__device__ int    g_cur[MAXN];
__device__ float4 g_slot[MAXEP];     // {src (bits), ea.x, ea.y, unused}
__device__ float  g_u[MAXN * CC];
__device__ float  g_v[MAXN * CC];
__device__ float  g_easum[2];
__device__ float  g_gc[CC];
__device__ int    g_total;

// ---- preprocessing ----
__global__ void k_zero(int N) {
    int i = blockIdx.x * blockDim.x + threadIdx.x;
    if (i < N) g_deg[i] = 0;
    if (i == 0) { g_easum[0] = 0.f; g_easum[1] = 0.f; g_total = 0; }
}

// fused: degree count (real edges) + edge_attr column sums
__global__ void k_deg_ea(const int* __restrict__ EI, const float* __restrict__ EA, int E) {
    __shared__ float s0[256], s1[256];
    int tid = threadIdx.x;
    float a0 = 0.f, a1 = 0.f;
    for (int e = blockIdx.x * 256 + tid; e < E; e += gridDim.x * 256) {
        atomicAdd(&g_deg[EI[E + e]], 1);
        float2 ea = ((const float2*)EA)[e];
        a0 += ea.x; a1 += ea.y;
    }
    s0[tid] = a0; s1[tid] = a1;
    __syncthreads();
    for (int s = 128; s; s >>= 1) {
        if (tid < s) { s0[tid] += s0[tid + s]; s1[tid] += s1[tid + s]; }
        __syncthreads();
    }
    if (tid == 0) {
        atomicAdd(&g_easum[0], s0[0]);
        atomicAdd(&g_easum[1], s1[0]);
    }
}

// atomic segment allocation (replaces prefix-sum scan); also places self-loop slot.
// Segment placement is run-varying but per-node content is identical -> same output.
__global__ void k_alloc(int N, float invE) {
    int i = blockIdx.x * blockDim.x + threadIdx.x;
    if (i >= N) return;
    int deg = g_deg[i];
    int o = atomicAdd(&g_total, deg + 1);
    g_off[i] = o;
    g_cur[i] = o;
    g_slot[o + deg] = make_float4(__int_as_float(i),
                                  g_easum[0] * invE, g_easum[1] * invE, 0.f);
}

__global__ void k_scatter(const int* __restrict__ EI, const float* __restrict__ EA, int E) {
    int e = blockIdx.x * blockDim.x + threadIdx.x;
    if (e >= E) return;
    int dst = EI[E + e];
    float2 ea = ((const float2*)EA)[e];
    int pos = atomicAdd(&g_cur[dst], 1);
    g_slot[pos] = make_float4(__int_as_float(EI[e]), ea.x, ea.y, 0.f);
}

// ---- node linears ----
__global__ void k_lin0(const float* __restrict__ x, const float* __restrict__ W0,
                       const float* __restrict__ b0, int N) {
    int i = blockIdx.x * blockDim.x + threadIdx.x;
    if (i >= N * HC) return;
    int n = i >> 6, j = i & 63;
    g_z[i] = fmaf(x[2 * n], W0[j], fmaf(x[2 * n + 1], W0[64 + j], b0[j]));
}

__global__ void k_lin64(const float* __restrict__ W, const float* __restrict__ b, int N) {
    __shared__ float sh[8][64];
    int gw = (blockIdx.x * blockDim.x + threadIdx.x) >> 5;
    int lane = threadIdx.x & 31;
    int wl = threadIdx.x >> 5;
    if (gw >= N) return;
    sh[wl][lane]      = g_hA[gw * 64 + lane];
    sh[wl][32 + lane] = g_hA[gw * 64 + 32 + lane];
    __syncwarp();
    float a0 = b[lane], a1 = b[32 + lane];
#pragma unroll
    for (int k = 0; k < 64; k++) {
        float hk = sh[wl][k];
        a0 = fmaf(hk, W[k * 64 + lane], a0);
        a1 = fmaf(hk, W[k * 64 + 32 + lane], a1);
    }
    g_z[gw * 64 + lane]      = a0;
    g_z[gw * 64 + 32 + lane] = a1;
}

// ---- fused GATv2: logits + online softmax + aggregation + ELU ----
// warp per destination node; lanes 0-15 = head0 (2 ch each), 16-31 = head1.
// Unroll 4: batched slot LDG.128 + 4 parallel z gathers, one rescale per group.
__global__ void __launch_bounds__(256) k_gatF(
        const float* __restrict__ We, const float* __restrict__ att,
        const float* __restrict__ bias, int outSel, int N) {
    int d = (blockIdx.x * blockDim.x + threadIdx.x) >> 5;
    int lane = threadIdx.x & 31;
    if (d >= N) return;
    float* __restrict__ hout = outSel ? g_hB : g_hA;
    const float2* __restrict__ z2 = (const float2*)g_z;

    int off0 = g_off[d];
    int deg = g_deg[d] + 1;              // includes self loop

    float2 zd  = z2[d * 32 + lane];
    float2 we0 = make_float2(We[lane * 2],      We[lane * 2 + 1]);
    float2 we1 = make_float2(We[64 + lane * 2], We[64 + lane * 2 + 1]);
    float2 at  = make_float2(att[lane * 2],     att[lane * 2 + 1]);

    float m = -1e30f, s = 0.f;
    float2 acc = make_float2(0.f, 0.f);

    int j = 0;
    for (; j + 4 <= deg; j += 4) {
        int b = off0 + j;
        float4 p0 = g_slot[b + 0];
        float4 p1 = g_slot[b + 1];
        float4 p2 = g_slot[b + 2];
        float4 p3 = g_slot[b + 3];
        int s0i = __float_as_int(p0.x);
        int s1i = __float_as_int(p1.x);
        int s2i = __float_as_int(p2.x);
        int s3i = __float_as_int(p3.x);
        float2 z0 = z2[s0i * 32 + lane];
        float2 z1 = z2[s1i * 32 + lane];
        float2 z2v = z2[s2i * 32 + lane];
        float2 z3 = z2[s3i * 32 + lane];

        float t0x = zd.x + z0.x + p0.y * we0.x + p0.z * we1.x;
        float t0y = zd.y + z0.y + p0.y * we0.y + p0.z * we1.y;
        float t1x = zd.x + z1.x + p1.y * we0.x + p1.z * we1.x;
        float t1y = zd.y + z1.y + p1.y * we0.y + p1.z * we1.y;
        float t2x = zd.x + z2v.x + p2.y * we0.x + p2.z * we1.x;
        float t2y = zd.y + z2v.y + p2.y * we0.y + p2.z * we1.y;
        float t3x = zd.x + z3.x + p3.y * we0.x + p3.z * we1.x;
        float t3y = zd.y + z3.y + p3.y * we0.y + p3.z * we1.y;
        t0x = (t0x > 0.f) ? t0x : 0.2f * t0x;  t0y = (t0y > 0.f) ? t0y : 0.2f * t0y;
        t1x = (t1x > 0.f) ? t1x : 0.2f * t1x;  t1y = (t1y > 0.f) ? t1y : 0.2f * t1y;
        t2x = (t2x > 0.f) ? t2x : 0.2f * t2x;  t2y = (t2y > 0.f) ? t2y : 0.2f * t2y;
        t3x = (t3x > 0.f) ? t3x : 0.2f * t3x;  t3y = (t3y > 0.f) ? t3y : 0.2f * t3y;

        float a0 = t0x * at.x + t0y * at.y;
        float a1 = t1x * at.x + t1y * at.y;
        float a2 = t2x * at.x + t2y * at.y;
        float a3 = t3x * at.x + t3y * at.y;
#pragma unroll
        for (int o = 1; o < 16; o <<= 1) {
            a0 += __shfl_xor_sync(0xffffffffu, a0, o);
            a1 += __shfl_xor_sync(0xffffffffu, a1, o);
            a2 += __shfl_xor_sync(0xffffffffu, a2, o);
            a3 += __shfl_xor_sync(0xffffffffu, a3, o);
        }

        float M = fmaxf(fmaxf(fmaxf(a0, a1), fmaxf(a2, a3)), m);
        float sc = __expf(m - M);
        float w0 = __expf(a0 - M);
        float w1 = __expf(a1 - M);
        float w2 = __expf(a2 - M);
        float w3 = __expf(a3 - M);
        s = s * sc + (w0 + w1) + (w2 + w3);
        acc.x = acc.x * sc + (w0 * z0.x + w1 * z1.x) + (w2 * z2v.x + w3 * z3.x);
        acc.y = acc.y * sc + (w0 * z0.y + w1 * z1.y) + (w2 * z2v.y + w3 * z3.y);
        m = M;
    }
    for (; j < deg; j++) {
        float4 p0 = g_slot[off0 + j];
        int s0i = __float_as_int(p0.x);
        float2 z0 = z2[s0i * 32 + lane];
        float t0x = zd.x + z0.x + p0.y * we0.x + p0.z * we1.x;
        float t0y = zd.y + z0.y + p0.y * we0.y + p0.z * we1.y;
        t0x = (t0x > 0.f) ? t0x : 0.2f * t0x;
        t0y = (t0y > 0.f) ? t0y : 0.2f * t0y;
        float a0 = t0x * at.x + t0y * at.y;
#pragma unroll
        for (int o = 1; o < 16; o <<= 1)
            a0 += __shfl_xor_sync(0xffffffffu, a0, o);
        float M = fmaxf(m, a0);
        float sc = __expf(m - M);
        float w0 = __expf(a0 - M);
        s = s * sc + w0;
        acc.x = acc.x * sc + w0 * z0.x;
        acc.y = acc.y * sc + w0 * z0.y;
        m = M;
    }

    float inv = 1.f / (s + 1e-16f);
    float2 bias2 = ((const float2*)bias)[lane];
    float o0 = acc.x * inv + bias2.x;
    float o1 = acc.y * inv + bias2.y;
    o0 = (o0 > 0.f) ? o0 : (__expf(o0) - 1.f);
    o1 = (o1 > 0.f) ? o1 : (__expf(o1) - 1.f);
    ((float2*)hout)[d * 32 + lane] = make_float2(o0, o1);
}

// ---- final edge MLP (factored) ----
__global__ void k_uv(const float* __restrict__ Wm1, int N) {
    __shared__ float sh[8][64];
    int gw = (blockIdx.x * blockDim.x + threadIdx.x) >> 5;
    int lane = threadIdx.x & 31;
    int wl = threadIdx.x >> 5;
    if (gw >= N) return;
    sh[wl][lane]      = g_hB[gw * 64 + lane];
    sh[wl][32 + lane] = g_hB[gw * 64 + 32 + lane];
    __syncwarp();
    float au = 0.f, av = 0.f;
#pragma unroll
    for (int k = 0; k < 64; k++) {
        float hk = sh[wl][k];
        au = fmaf(hk, Wm1[k * 32 + lane], au);
        av = fmaf(hk, Wm1[(64 + k) * 32 + lane], av);
    }
    g_u[gw * 32 + lane] = au;
    g_v[gw * 32 + lane] = av;
}

__global__ void k_goal(const float* __restrict__ Wm1, const float* __restrict__ bm1,
                       const int* __restrict__ dest) {
    int lane = threadIdx.x;
    int d = dest[0];
    float acc = bm1[lane];
    for (int k = 0; k < 64; k++)
        acc = fmaf(g_hB[d * 64 + k], Wm1[(128 + k) * 32 + lane], acc);
    g_gc[lane] = acc;
}

// 2 edges per warp, float2 channel lanes
__global__ void k_edge(const int* __restrict__ EI, const float* __restrict__ EA,
                       const float* __restrict__ Wm1, const float* __restrict__ Wm2,
                       const float* __restrict__ bm2, float* __restrict__ out, int E) {
    int warpId = (blockIdx.x * blockDim.x + threadIdx.x) >> 5;
    int lane = threadIdx.x & 31;
    int sub = lane & 15;
    if (warpId * 2 >= E) return;
    int e = warpId * 2 + (lane >> 4);
    bool valid = (e < E);
    if (!valid) e = E - 1;

    int src = EI[e], dst = EI[E + e];
    float2 ea = ((const float2*)EA)[e];
    float2 u2 = ((const float2*)g_u)[src * 16 + sub];
    float2 v2 = ((const float2*)g_v)[dst * 16 + sub];
    float2 gc2 = ((const float2*)g_gc)[sub];
    float2 wa  = ((const float2*)(Wm1 + 192 * 32))[sub];
    float2 wb  = ((const float2*)(Wm1 + 193 * 32))[sub];
    float2 wm2 = ((const float2*)Wm2)[sub];

    float t0 = u2.x + v2.x + gc2.x + ea.x * wa.x + ea.y * wb.x;
    float t1 = u2.y + v2.y + gc2.y + ea.x * wa.y + ea.y * wb.y;
    t0 = fmaxf(t0, 0.f);
    t1 = fmaxf(t1, 0.f);
    float p = t0 * wm2.x + t1 * wm2.y;
    p += __shfl_xor_sync(0xffffffffu, p, 1);
    p += __shfl_xor_sync(0xffffffffu, p, 2);
    p += __shfl_xor_sync(0xffffffffu, p, 4);
    p += __shfl_xor_sync(0xffffffffu, p, 8);
    if (sub == 0 && valid) out[e] = p + __ldg(bm2);
}

extern "C" void kernel_launch(void* const* d_in, const int* in_sizes, int n_in,
                              void* d_out, int out_size) {
    const float* x     = (const float*)d_in[0];
    const int*   EI    = (const int*)  d_in[1];
    const float* EA    = (const float*)d_in[2];
    const int*   dest  = (const int*)  d_in[3];
    const float* W0    = (const float*)d_in[4];
    const float* b0    = (const float*)d_in[5];
    const float* We0   = (const float*)d_in[6];
    const float* att0  = (const float*)d_in[7];
    const float* bias0 = (const float*)d_in[8];
    const float* W1    = (const float*)d_in[9];
    const float* b1    = (const float*)d_in[10];
    const float* We1   = (const float*)d_in[11];
    const float* att1  = (const float*)d_in[12];
    const float* bias1 = (const float*)d_in[13];
    const float* Wm1   = (const float*)d_in[14];
    const float* bm1   = (const float*)d_in[15];
    const float* Wm2   = (const float*)d_in[16];
    const float* bm2   = (const float*)d_in[17];

    int N  = in_sizes[0] / 2;
    int E  = in_sizes[1] / 2;
    float invE = 1.0f / (float)E;
    float* out = (float*)d_out;

    // CSR build (atomic range allocation, no prefix scan)
    k_zero   <<<(N + 255) / 256, 256>>>(N);
    k_deg_ea <<<512, 256>>>(EI, EA, E);
    k_alloc  <<<(N + 255) / 256, 256>>>(N, invE);
    k_scatter<<<(E + 255) / 256, 256>>>(EI, EA, E);

    int nodeBlocks = (N + 7) / 8;

    // layer 0
    k_lin0 <<<(N * 64 + 255) / 256, 256>>>(x, W0, b0, N);
    k_gatF <<<nodeBlocks, 256>>>(We0, att0, bias0, /*outSel=*/0, N);

    // layer 1
    k_lin64<<<nodeBlocks, 256>>>(W1, b1, N);
    k_gatF <<<nodeBlocks, 256>>>(We1, att1, bias1, /*outSel=*/1, N);

    // edge MLP
    k_uv   <<<nodeBlocks, 256>>>(Wm1, N);
    k_goal <<<1, 32>>>(Wm1, bm1, dest);
    k_edge <<<(E + 15) / 16, 256>>>(EI, EA, Wm1, Wm2, bm2, out, E);
}